// round 1
// baseline (speedup 1.0000x reference)
#include <cuda_runtime.h>
#include <math.h>

#define H 2048
#define W 2048
#define OH 2046
#define OW 2046
#define TILE 32
#define HALO 34
#define SROW 36           // padded shared row stride (floats)
#define GBX 64
#define GBY 64
#define NBLK (GBX * GBY)  // 4096

// Deterministic per-block partials (no atomics -> bitwise-stable across replays)
__device__ double g_part_loss[NBLK];
__device__ double g_part_esum[NBLK];

__global__ __launch_bounds__(256, 4)
void inverse_loss_main(const float* __restrict__ predE,
                       const float* __restrict__ predV,
                       const float* __restrict__ strain)
{
    __shared__ float sE [HALO * SROW];
    __shared__ float sXX[HALO * SROW];
    __shared__ float sYY[HALO * SROW];
    __shared__ float sXY[HALO * SROW];

    const int tid = threadIdx.y * 32 + threadIdx.x;
    const int oy0 = blockIdx.y * TILE;
    const int ox0 = blockIdx.x * TILE;

    // ---- load halo tile, compute stresses on the fly ----
    for (int idx = tid; idx < HALO * HALO; idx += 256) {
        const int y = idx / HALO;
        const int x = idx - y * HALO;
        const int gy = oy0 + y;
        const int gx = ox0 + x;
        float e = 0.f, sxx = 0.f, syy = 0.f, sxy = 0.f;
        if (gy < H && gx < W) {
            const int g = gy * W + gx;
            e = predE[g];
            const float vv  = predV[g];
            const float exx = strain[3 * g + 0];
            const float eyy = strain[3 * g + 1];
            const float exy = strain[3 * g + 2];
            const float frac = e / (1.0f - vv * vv);
            sxx = (exx + vv * eyy) * frac;
            syy = (vv * exx + eyy) * frac;
            sxy = exy * (1.0f - vv) * 0.5f * frac;
        }
        const int s = y * SROW + x;
        sE[s] = e; sXX[s] = sxx; sYY[s] = syy; sXY[s] = sxy;
    }
    __syncthreads();

    // ---- stencil: each thread = 1 column x 4 consecutive output rows ----
    const int lx     = threadIdx.x;
    const int lybase = threadIdx.y * 4;

    float rsE[6], rsXX[6], rsXY[6], dYY[6], dXY[6];
    #pragma unroll
    for (int r = 0; r < 6; r++) {
        const int base = (lybase + r) * SROW + lx;
        const float e0 = sE[base],  e1 = sE[base + 1],  e2 = sE[base + 2];
        rsE[r] = e0 + e1 + e2;
        const float a0 = sXX[base], a1 = sXX[base + 1], a2 = sXX[base + 2];
        rsXX[r] = a0 + a1 + a2;
        const float b0 = sYY[base],                     b2 = sYY[base + 2];
        dYY[r] = b0 - b2;
        const float c0 = sXY[base], c1 = sXY[base + 1], c2 = sXY[base + 2];
        dXY[r]  = c0 - c2;
        rsXY[r] = c0 + c1 + c2;
    }

    float lsum = 0.f;
    const int ox = ox0 + lx;
    #pragma unroll
    for (int k = 0; k < 4; k++) {
        const int oy = oy0 + lybase + k;
        if (oy < OH && ox < OW) {
            const float Ec = rsE[k] + rsE[k + 1] + rsE[k + 2];
            // fx = (row2 - row0) 3-col sums of s_xx  +  (col0 - col2) 3-row sums of s_xy
            const float fx = (rsXX[k + 2] - rsXX[k]) + (dXY[k] + dXY[k + 1] + dXY[k + 2]);
            // fy = (col0 - col2) 3-row sums of s_yy  +  (row2 - row0) 3-col sums of s_xy
            const float fy = (dYY[k] + dYY[k + 1] + dYY[k + 2]) + (rsXY[k + 2] - rsXY[k]);
            lsum += (fabsf(fx) + fabsf(fy)) / Ec;
        }
    }

    // ---- E mean contribution: exact float4 partition, 4 elems/thread ----
    const int bid = blockIdx.y * gridDim.x + blockIdx.x;
    float esum;
    {
        const float4* E4 = reinterpret_cast<const float4*>(predE);
        const float4 q = E4[(size_t)bid * 256 + tid];   // 4096*256 threads == N/4 exactly
        esum = (q.x + q.y) + (q.z + q.w);
    }

    // ---- block reduction (warp shuffle -> shared -> thread 0) ----
    #pragma unroll
    for (int o = 16; o > 0; o >>= 1) {
        lsum += __shfl_down_sync(0xffffffffu, lsum, o);
        esum += __shfl_down_sync(0xffffffffu, esum, o);
    }
    __shared__ float wl[8], we[8];
    if ((tid & 31) == 0) { wl[tid >> 5] = lsum; we[tid >> 5] = esum; }
    __syncthreads();
    if (tid == 0) {
        double L = 0.0, Es = 0.0;
        #pragma unroll
        for (int i = 0; i < 8; i++) { L += (double)wl[i]; Es += (double)we[i]; }
        g_part_loss[bid] = L;
        g_part_esum[bid] = Es;
    }
}

__global__ void inverse_loss_finalize(float* __restrict__ out)
{
    __shared__ double sl[256], se[256];
    const int t = threadIdx.x;
    double L = 0.0, E = 0.0;
    for (int i = t; i < NBLK; i += 256) {
        L += g_part_loss[i];
        E += g_part_esum[i];
    }
    sl[t] = L; se[t] = E;
    __syncthreads();
    for (int s = 128; s > 0; s >>= 1) {
        if (t < s) { sl[t] += sl[t + s]; se[t] += se[t + s]; }
        __syncthreads();
    }
    if (t == 0) {
        const double M = (double)OH * (double)OW;
        const double meanE = se[0] / ((double)H * (double)W);
        out[0] = (float)(sl[0] / M + fabs(meanE - 1.0) / 100.0);
    }
}

extern "C" void kernel_launch(void* const* d_in, const int* in_sizes, int n_in,
                              void* d_out, int out_size)
{
    const float* predE  = (const float*)d_in[0];
    const float* predV  = (const float*)d_in[1];
    const float* strain = (const float*)d_in[2];
    float* out = (float*)d_out;

    dim3 block(32, 8);
    dim3 grid(GBX, GBY);
    inverse_loss_main<<<grid, block>>>(predE, predV, strain);
    inverse_loss_finalize<<<1, 256>>>(out);
}